// round 7
// baseline (speedup 1.0000x reference)
#include <cuda_runtime.h>
#include <cuda_bf16.h>
#include <cstdint>

// ============================================================
// x(16384,128) f32, p(16384,8) f32, W(128,4096) f32, b(4096) f32
// logits[b,n] = sum_f x[b,f]*W[f,n],  n = c*512 + d*64 + r
// out[b, d*64+r] = sum_c p[b,c] * softmax_d(logits[b,c,:,r])
//
// bf16x3-split warp-level mma.sync (HMMA) GEMM, columns permuted
// n' = r*64 + c*8 + d so each n8 mma tile is one softmax d-group.
// R7: 512 threads / 16 warps (4m x 4n), warp tile 32x64 -> acc 64
// regs, 4 warps/SMSP for latency hiding.
// ============================================================

#define NF 128

// -------- device scratch --------
__device__ __align__(1024) uint8_t g_Whi[32u * 32768];   // [slab*2+kh][256n][8ch][16B]
__device__ __align__(1024) uint8_t g_Wlo[32u * 32768];
__device__ __align__(1024) uint8_t g_Xhi[128u * 32768];  // [rowblk][128r][16ch][16B]
__device__ __align__(1024) uint8_t g_Xlo[128u * 32768];
__device__ __align__(16) float g_biasp[4096];

// -------- smem byte offsets --------
#define SM_XHI   0
#define SM_XLO   32768
#define SM_W     65536            // 2 slots x 65536 (hi 32K + lo 32K each)
#define SM_STAGE 131072           // = slot 1 (reused after its HMMAs drain)
#define SM_BIAS  196608
#define SM_P     212992
#define SM_TOT   217088

__device__ __forceinline__ uint32_t smem_u32(const void* p) {
    return (uint32_t)__cvta_generic_to_shared(p);
}
__device__ __forceinline__ void cp16(uint32_t dst, const void* src) {
    asm volatile("cp.async.cg.shared.global [%0], [%1], 16;" :: "r"(dst), "l"(src));
}
#define LDSM4(r, a) \
    asm volatile("ldmatrix.sync.aligned.m8n8.x4.shared.b16 {%0,%1,%2,%3}, [%4];" \
        : "=r"((r)[0]), "=r"((r)[1]), "=r"((r)[2]), "=r"((r)[3]) : "r"(a))

__device__ __forceinline__ void mma16816(float* c, const uint32_t* a,
                                         uint32_t b0, uint32_t b1) {
    asm volatile(
        "mma.sync.aligned.m16n8k16.row.col.f32.bf16.bf16.f32 "
        "{%0,%1,%2,%3}, {%4,%5,%6,%7}, {%8,%9}, {%0,%1,%2,%3};"
        : "+f"(c[0]), "+f"(c[1]), "+f"(c[2]), "+f"(c[3])
        : "r"(a[0]), "r"(a[1]), "r"(a[2]), "r"(a[3]), "r"(b0), "r"(b1));
}
__device__ __forceinline__ uint32_t pack2bf(float a, float b) {
    __nv_bfloat162 h;
    h.x = __float2bfloat16(a);
    h.y = __float2bfloat16(b);
    return *reinterpret_cast<uint32_t*>(&h);
}

// ============================================================
// Prep: W -> permuted, split, swizzled images; bias -> permuted
// ============================================================
__global__ void prep_w_kernel(const float* __restrict__ W,
                              const float* __restrict__ bias) {
    int idx = blockIdx.x * 256 + threadIdx.x;   // 64*4096
    if (idx < 4096) {
        int n = idx;
        int c = n >> 9, d = (n >> 6) & 7, r = n & 63;
        g_biasp[r * 64 + c * 8 + d] = bias[n];
    }
    int f2 = (idx >> 12) * 2;                   // even feature
    int n  = idx & 4095;
    float w0 = W[(size_t)f2 * 4096 + n];
    float w1 = W[(size_t)(f2 + 1) * 4096 + n];
    float h0 = __bfloat162float(__float2bfloat16(w0));
    float h1 = __bfloat162float(__float2bfloat16(w1));
    int c = n >> 9, d = (n >> 6) & 7, r = n & 63;
    int np = r * 64 + c * 8 + d;                // permuted column
    int slab = np >> 8, nl = np & 255;
    int kh = f2 >> 6, kl = f2 & 63;
    int ch = kl >> 3;
    uint32_t off = (uint32_t)(nl * 128 + (((ch ^ (nl & 7)) & 7) << 4) + (kl & 7) * 2);
    size_t base = ((size_t)slab * 2 + kh) * 32768 + off;
    *(uint32_t*)(g_Whi + base) = pack2bf(h0, h1);
    *(uint32_t*)(g_Wlo + base) = pack2bf(w0 - h0, w1 - h1);
}

__global__ void prep_x_kernel(const float* __restrict__ X) {
    int idx = blockIdx.x * 256 + threadIdx.x;   // 16384*64
    int row = idx >> 6;
    int k2  = (idx & 63) * 2;
    float2 v = *reinterpret_cast<const float2*>(X + (size_t)row * NF + k2);
    float h0 = __bfloat162float(__float2bfloat16(v.x));
    float h1 = __bfloat162float(__float2bfloat16(v.y));
    int blk = row >> 7, rl = row & 127;
    int ch = k2 >> 3;
    uint32_t off = (uint32_t)(rl * 256 + ((ch ^ (rl & 7)) << 4) + (k2 & 7) * 2);
    *(uint32_t*)(g_Xhi + (size_t)blk * 32768 + off) = pack2bf(h0, h1);
    *(uint32_t*)(g_Xlo + (size_t)blk * 32768 + off) = pack2bf(v.x - h0, v.y - h1);
}

// ============================================================
// Main kernel: 128 CTAs x 512 threads, warp grid 4(m) x 4(n)
// ============================================================
__global__ __launch_bounds__(512, 1)
void crowds_mma_kernel(const float* __restrict__ p, float* __restrict__ out) {
    extern __shared__ __align__(1024) uint8_t smem[];
    const uint32_t sb = smem_u32(smem);
    float* biasS = (float*)(smem + SM_BIAS);
    float* psS   = (float*)(smem + SM_P);
    float* stage = (float*)(smem + SM_STAGE);

    const int tid = threadIdx.x, lane = tid & 31, warp = tid >> 5;
    const int wm = warp >> 2, wn = warp & 3;    // warp tile 32 x 64
    const int rowbase = blockIdx.x * 128;

    // ---- initial loads: X hi/lo, bias, W image 0; p transpose ----
    {
        const uint8_t* gxh = g_Xhi + (size_t)blockIdx.x * 32768;
        const uint8_t* gxl = g_Xlo + (size_t)blockIdx.x * 32768;
        #pragma unroll
        for (int i = 0; i < 4; i++) {
            int o = (tid + i * 512) * 16;
            cp16(sb + SM_XHI + o, gxh + o);
            cp16(sb + SM_XLO + o, gxl + o);
            cp16(sb + SM_W + o, g_Whi + o);
            cp16(sb + SM_W + 32768 + o, g_Wlo + o);
        }
        #pragma unroll
        for (int i = 0; i < 2; i++) {
            int o = (tid + i * 512) * 16;
            cp16(sb + SM_BIAS + o, (const uint8_t*)g_biasp + o);
        }
        asm volatile("cp.async.commit_group;");
        #pragma unroll
        for (int i = 0; i < 2; i++) {
            int ii = tid + i * 512;
            int row = ii >> 3, c = ii & 7;
            psS[c * 128 + row] = p[(size_t)(rowbase + row) * 8 + c];
        }
    }

    float acc[2][8][4];

    for (int j = 0; j < 32; j++) {
        const int slab = j >> 1, kh = j & 1, slot = j & 1;

        // prefetch next W image
        if (j + 1 < 32) {
            const uint8_t* sh = g_Whi + (size_t)(j + 1) * 32768;
            const uint8_t* sl = g_Wlo + (size_t)(j + 1) * 32768;
            uint32_t dst = sb + SM_W + ((j + 1) & 1) * 65536;
            #pragma unroll
            for (int i = 0; i < 4; i++) {
                int o = (tid + i * 512) * 16;
                cp16(dst + o, sh + o);
                cp16(dst + 32768 + o, sl + o);
            }
            asm volatile("cp.async.commit_group;");
            asm volatile("cp.async.wait_group 1;");
        } else {
            asm volatile("cp.async.wait_group 0;");
        }
        __syncthreads();

        if (kh == 0) {
            #pragma unroll
            for (int mt = 0; mt < 2; mt++)
                #pragma unroll
                for (int nt = 0; nt < 8; nt++)
                    #pragma unroll
                    for (int e = 0; e < 4; e++) acc[mt][nt][e] = 0.f;
        }

        const uint32_t wslot = sb + SM_W + slot * 65536;
        const int arow_base = wm * 32 + (lane & 7) + ((lane >> 3) & 1) * 8;
        const int bn0 = wn * 64 + (lane & 7) + ((lane >> 4) << 3);

        #pragma unroll
        for (int ks = 0; ks < 4; ks++) {
            uint32_t ahi[2][4], alo[2][4];
            const int xch = kh * 8 + ks * 2 + (lane >> 4);
            #pragma unroll
            for (int mt = 0; mt < 2; mt++) {
                int row = arow_base + mt * 16;
                uint32_t aoff = (uint32_t)(row * 256 + ((xch ^ (row & 7)) << 4));
                LDSM4(ahi[mt], sb + SM_XHI + aoff);
                LDSM4(alo[mt], sb + SM_XLO + aoff);
            }
            const int bch = ks * 2 + ((lane >> 3) & 1);
            #pragma unroll
            for (int t2 = 0; t2 < 4; t2++) {
                uint32_t bh[4], bl[4];
                int n = bn0 + t2 * 16;
                uint32_t boff = (uint32_t)(n * 128 + (((bch ^ (n & 7)) & 7) << 4));
                LDSM4(bh, wslot + boff);
                LDSM4(bl, wslot + 32768 + boff);
                #pragma unroll
                for (int mt = 0; mt < 2; mt++)
                    #pragma unroll
                    for (int hf = 0; hf < 2; hf++) {
                        float* cacc = acc[mt][t2 * 2 + hf];
                        mma16816(cacc, ahi[mt], bh[hf * 2], bh[hf * 2 + 1]);
                        mma16816(cacc, ahi[mt], bl[hf * 2], bl[hf * 2 + 1]);
                        mma16816(cacc, alo[mt], bh[hf * 2], bh[hf * 2 + 1]);
                    }
            }
        }

        // ---- epilogue at slab end: softmax over d (quad shuffles) + p ----
        // This warp's 64 cols = one r value: r = slab*4 + wn; nt == c.
        if (kh == 1) {
            const int q = lane & 3, rowq = lane >> 2;
            float of[2][4];
            #pragma unroll
            for (int mt = 0; mt < 2; mt++)
                #pragma unroll
                for (int e = 0; e < 4; e++) of[mt][e] = 0.f;

            #pragma unroll
            for (int mt = 0; mt < 2; mt++) {
                const int row0 = wm * 32 + mt * 16 + rowq;
                #pragma unroll
                for (int c = 0; c < 8; c++) {
                    const int nb_abs = slab * 256 + wn * 64 + c * 8;
                    float2 bv = *(const float2*)&biasS[nb_abs + q * 2];
                    float e0 = __expf(acc[mt][c][0] + bv.x);
                    float e1 = __expf(acc[mt][c][1] + bv.y);
                    float e2 = __expf(acc[mt][c][2] + bv.x);
                    float e3 = __expf(acc[mt][c][3] + bv.y);
                    float s0 = e0 + e1, s1 = e2 + e3;
                    s0 += __shfl_xor_sync(0xffffffffu, s0, 1);
                    s0 += __shfl_xor_sync(0xffffffffu, s0, 2);
                    s1 += __shfl_xor_sync(0xffffffffu, s1, 1);
                    s1 += __shfl_xor_sync(0xffffffffu, s1, 2);
                    float f0 = __fdividef(psS[c * 128 + row0], s0);
                    float f1 = __fdividef(psS[c * 128 + row0 + 8], s1);
                    of[mt][0] = fmaf(e0, f0, of[mt][0]);
                    of[mt][1] = fmaf(e1, f0, of[mt][1]);
                    of[mt][2] = fmaf(e2, f1, of[mt][2]);
                    of[mt][3] = fmaf(e3, f1, of[mt][3]);
                }
            }
            __syncthreads();   // all warps done reading slot1 before stage reuse

            #pragma unroll
            for (int mt = 0; mt < 2; mt++) {
                const int row0 = wm * 32 + mt * 16 + rowq;
                stage[row0 * 32 + (2 * q) * 4 + wn]           = of[mt][0];
                stage[row0 * 32 + (2 * q + 1) * 4 + wn]       = of[mt][1];
                stage[(row0 + 8) * 32 + (2 * q) * 4 + wn]     = of[mt][2];
                stage[(row0 + 8) * 32 + (2 * q + 1) * 4 + wn] = of[mt][3];
            }
            __syncthreads();

            #pragma unroll
            for (int w = 0; w < 2; w++) {
                int i = tid + w * 512;
                int row = i >> 3, d = i & 7;
                float4 v = *(const float4*)&stage[row * 32 + d * 4];
                *(float4*)&out[(size_t)(rowbase + row) * 512 + d * 64 + slab * 4] = v;
            }
        }
        __syncthreads();       // slot j&1 free for prefetch issued next iter
    }
}

// ============================================================
extern "C" void kernel_launch(void* const* d_in, const int* in_sizes, int n_in,
                              void* d_out, int out_size) {
    const float* x    = (const float*)d_in[0];
    const float* p    = (const float*)d_in[1];
    const float* W    = (const float*)d_in[2];
    const float* bias = (const float*)d_in[3];
    float* out = (float*)d_out;

    int B = in_sizes[0] / NF;                    // 16384

    prep_w_kernel<<<(64 * 4096) / 256, 256>>>(W, bias);
    prep_x_kernel<<<(B * 64) / 256, 256>>>(x);

    cudaFuncSetAttribute(crowds_mma_kernel,
                         cudaFuncAttributeMaxDynamicSharedMemorySize, SM_TOT);
    crowds_mma_kernel<<<B / 128, 512, SM_TOT>>>(p, out);
}

// round 8
// speedup vs baseline: 1.3488x; 1.3488x over previous
#include <cuda_runtime.h>
#include <cuda_fp16.h>
#include <cstdint>

// ============================================================
// x(16384,128) f32, p(16384,8) f32, W(128,4096) f32, b(4096) f32
// logits[b,n] = sum_f x[b,f]*W[f,n],  n = c*512 + d*64 + r
// out[b, d*64+r] = sum_c p[b,c] * softmax_d(logits[b,c,:,r])
//
// fp16 2-term split (x = xh + xl exact, W single-rounded fp16):
//   logits = xh*W + xl*W   (fp32 accum)  -> out rel err ~1e-4
// mma.sync m16n8k16 HMMA, columns permuted n' = r*64 + c*8 + d so
// each n8 tile is one softmax d-group (2 quad shuffles).
// Single merged prep kernel (2 launches/call -> ncu hits main).
// ============================================================

#define NF 128

// -------- device scratch --------
__device__ __align__(1024) uint8_t g_Wh[32u * 32768];    // [slab*2+kh][256n][8ch][16B] fp16
__device__ __align__(1024) uint8_t g_Xhi[128u * 32768];  // [rowblk][128r][16ch][16B] fp16
__device__ __align__(1024) uint8_t g_Xlo[128u * 32768];
__device__ __align__(16) float g_biasp[4096];

// -------- smem byte offsets --------
#define SM_XHI   0
#define SM_XLO   32768
#define SM_W     65536            // 2 slots x 32768
#define SM_BIAS  131072           // 16384
#define SM_STAGE 147456           // 16384 (dedicated, no aliasing)
#define SM_P     163840           // 4096
#define SM_TOT   167936

__device__ __forceinline__ uint32_t smem_u32(const void* p) {
    return (uint32_t)__cvta_generic_to_shared(p);
}
__device__ __forceinline__ void cp16(uint32_t dst, const void* src) {
    asm volatile("cp.async.cg.shared.global [%0], [%1], 16;" :: "r"(dst), "l"(src));
}
#define LDSM4(r, a) \
    asm volatile("ldmatrix.sync.aligned.m8n8.x4.shared.b16 {%0,%1,%2,%3}, [%4];" \
        : "=r"((r)[0]), "=r"((r)[1]), "=r"((r)[2]), "=r"((r)[3]) : "r"(a))

__device__ __forceinline__ void mma16816h(float* c, const uint32_t* a,
                                          uint32_t b0, uint32_t b1) {
    asm volatile(
        "mma.sync.aligned.m16n8k16.row.col.f32.f16.f16.f32 "
        "{%0,%1,%2,%3}, {%4,%5,%6,%7}, {%8,%9}, {%0,%1,%2,%3};"
        : "+f"(c[0]), "+f"(c[1]), "+f"(c[2]), "+f"(c[3])
        : "r"(a[0]), "r"(a[1]), "r"(a[2]), "r"(a[3]), "r"(b0), "r"(b1));
}
__device__ __forceinline__ uint32_t pack2h(float a, float b) {
    __half2 h;
    h.x = __float2half_rn(a);
    h.y = __float2half_rn(b);
    return *reinterpret_cast<uint32_t*>(&h);
}

// ============================================================
// Merged prep: W -> permuted fp16 image; x -> fp16 hi/lo split
// images; bias -> permuted. One kernel, 4096 blocks x 256.
// ============================================================
__global__ void prep_kernel(const float* __restrict__ X,
                            const float* __restrict__ W,
                            const float* __restrict__ bias) {
    int idx = blockIdx.x * 256 + threadIdx.x;   // 0 .. 1048575

    if (idx < 4096) {
        int n = idx;
        int c = n >> 9, d = (n >> 6) & 7, r = n & 63;
        g_biasp[r * 64 + c * 8 + d] = bias[n];
    }

    if (idx < 64 * 4096) {                      // W: 262144 k-pair x n items
        int f2 = (idx >> 12) * 2;
        int n  = idx & 4095;
        float w0 = W[(size_t)f2 * 4096 + n];
        float w1 = W[(size_t)(f2 + 1) * 4096 + n];
        int c = n >> 9, d = (n >> 6) & 7, r = n & 63;
        int np = r * 64 + c * 8 + d;            // permuted column
        int slab = np >> 8, nl = np & 255;
        int kh = f2 >> 6, kl = f2 & 63;
        int ch = kl >> 3;
        uint32_t off = (uint32_t)(nl * 128 + (((ch ^ (nl & 7)) & 7) << 4) + (kl & 7) * 2);
        *(uint32_t*)(g_Wh + ((size_t)slab * 2 + kh) * 32768 + off) = pack2h(w0, w1);
    }

    // x split: every thread handles one (row, k-pair)
    {
        int row = idx >> 6;
        int k2  = (idx & 63) * 2;
        float2 v = *reinterpret_cast<const float2*>(X + (size_t)row * NF + k2);
        float h0 = __half2float(__float2half_rn(v.x));
        float h1 = __half2float(__float2half_rn(v.y));
        int blk = row >> 7, rl = row & 127;
        int ch = k2 >> 3;
        uint32_t off = (uint32_t)(rl * 256 + ((ch ^ (rl & 7)) << 4) + (k2 & 7) * 2);
        *(uint32_t*)(g_Xhi + (size_t)blk * 32768 + off) = pack2h(v.x, v.y);
        *(uint32_t*)(g_Xlo + (size_t)blk * 32768 + off) = pack2h(v.x - h0, v.y - h1);
    }
}

// ============================================================
// Main kernel: 128 CTAs x 256 threads, warp grid 4(m) x 2(n)
// ============================================================
__global__ __launch_bounds__(256, 1)
void crowds_mma_kernel(const float* __restrict__ p, float* __restrict__ out) {
    extern __shared__ __align__(1024) uint8_t smem[];
    const uint32_t sb = smem_u32(smem);
    float* biasS = (float*)(smem + SM_BIAS);
    float* psS   = (float*)(smem + SM_P);
    float* stage = (float*)(smem + SM_STAGE);

    const int tid = threadIdx.x, lane = tid & 31, warp = tid >> 5;
    const int wm = warp >> 1, wn = warp & 1;    // warp tile 32 x 128
    const int rowbase = blockIdx.x * 128;

    // ---- initial loads: X hi/lo, W image 0, bias; p transpose ----
    {
        const uint8_t* gxh = g_Xhi + (size_t)blockIdx.x * 32768;
        const uint8_t* gxl = g_Xlo + (size_t)blockIdx.x * 32768;
        #pragma unroll
        for (int i = 0; i < 8; i++) {
            int o = (tid + i * 256) * 16;
            cp16(sb + SM_XHI + o, gxh + o);
            cp16(sb + SM_XLO + o, gxl + o);
            cp16(sb + SM_W + o, g_Wh + o);
        }
        #pragma unroll
        for (int i = 0; i < 4; i++) {
            int o = (tid + i * 256) * 16;
            cp16(sb + SM_BIAS + o, (const uint8_t*)g_biasp + o);
        }
        asm volatile("cp.async.commit_group;");
        #pragma unroll
        for (int i = 0; i < 4; i++) {
            int ii = tid + i * 256;
            int row = ii >> 3, c = ii & 7;
            psS[c * 128 + row] = p[(size_t)(rowbase + row) * 8 + c];
        }
    }

    float acc[2][16][4];

    for (int j = 0; j < 32; j++) {
        const int slab = j >> 1, kh = j & 1, slot = j & 1;

        // prefetch next W image
        if (j + 1 < 32) {
            const uint8_t* sh = g_Wh + (size_t)(j + 1) * 32768;
            uint32_t dst = sb + SM_W + ((j + 1) & 1) * 32768;
            #pragma unroll
            for (int i = 0; i < 8; i++) {
                int o = (tid + i * 256) * 16;
                cp16(dst + o, sh + o);
            }
            asm volatile("cp.async.commit_group;");
            asm volatile("cp.async.wait_group 1;");
        } else {
            asm volatile("cp.async.wait_group 0;");
        }
        __syncthreads();

        if (kh == 0) {
            #pragma unroll
            for (int mt = 0; mt < 2; mt++)
                #pragma unroll
                for (int nt = 0; nt < 16; nt++)
                    #pragma unroll
                    for (int e = 0; e < 4; e++) acc[mt][nt][e] = 0.f;
        }

        const uint32_t wslot = sb + SM_W + slot * 32768;
        const int arow_base = wm * 32 + (lane & 7) + ((lane >> 3) & 1) * 8;
        const int bn0 = wn * 128 + (lane & 7) + ((lane >> 4) << 3);

        #pragma unroll
        for (int ks = 0; ks < 4; ks++) {
            uint32_t ahi[2][4], alo[2][4];
            const int xch = kh * 8 + ks * 2 + (lane >> 4);
            #pragma unroll
            for (int mt = 0; mt < 2; mt++) {
                int row = arow_base + mt * 16;
                uint32_t aoff = (uint32_t)(row * 256 + ((xch ^ (row & 7)) << 4));
                LDSM4(ahi[mt], sb + SM_XHI + aoff);
                LDSM4(alo[mt], sb + SM_XLO + aoff);
            }
            const int bch = ks * 2 + ((lane >> 3) & 1);
            #pragma unroll
            for (int nb = 0; nb < 2; nb++) {
                #pragma unroll
                for (int t2 = 0; t2 < 4; t2++) {
                    uint32_t bh[4];
                    int n = bn0 + nb * 64 + t2 * 16;
                    uint32_t boff = (uint32_t)(n * 128 + (((bch ^ (n & 7)) & 7) << 4));
                    LDSM4(bh, wslot + boff);
                    #pragma unroll
                    for (int mt = 0; mt < 2; mt++)
                        #pragma unroll
                        for (int hf = 0; hf < 2; hf++) {
                            float* cacc = acc[mt][nb * 8 + t2 * 2 + hf];
                            mma16816h(cacc, ahi[mt], bh[hf * 2], bh[hf * 2 + 1]);
                            mma16816h(cacc, alo[mt], bh[hf * 2], bh[hf * 2 + 1]);
                        }
                }
            }
        }

        // ---- epilogue at slab end: softmax over d (quad shuffles) + p ----
        if (kh == 1) {
            const int q = lane & 3, rowq = lane >> 2;
            float of[2][2][4];
            #pragma unroll
            for (int mt = 0; mt < 2; mt++)
                #pragma unroll
                for (int rb = 0; rb < 2; rb++)
                    #pragma unroll
                    for (int e = 0; e < 4; e++) of[mt][rb][e] = 0.f;

            #pragma unroll
            for (int mt = 0; mt < 2; mt++) {
                const int row0 = wm * 32 + mt * 16 + rowq;
                #pragma unroll
                for (int nt = 0; nt < 16; nt++) {
                    const int c = nt & 7, rb = nt >> 3;
                    const int nb_abs = slab * 256 + wn * 128 + nt * 8;
                    float2 bv = *(const float2*)&biasS[nb_abs + q * 2];
                    float e0 = __expf(acc[mt][nt][0] + bv.x);
                    float e1 = __expf(acc[mt][nt][1] + bv.y);
                    float e2 = __expf(acc[mt][nt][2] + bv.x);
                    float e3 = __expf(acc[mt][nt][3] + bv.y);
                    float s0 = e0 + e1, s1 = e2 + e3;
                    s0 += __shfl_xor_sync(0xffffffffu, s0, 1);
                    s0 += __shfl_xor_sync(0xffffffffu, s0, 2);
                    s1 += __shfl_xor_sync(0xffffffffu, s1, 1);
                    s1 += __shfl_xor_sync(0xffffffffu, s1, 2);
                    float f0 = __fdividef(psS[c * 128 + row0], s0);
                    float f1 = __fdividef(psS[c * 128 + row0 + 8], s1);
                    of[mt][rb][0] = fmaf(e0, f0, of[mt][rb][0]);
                    of[mt][rb][1] = fmaf(e1, f0, of[mt][rb][1]);
                    of[mt][rb][2] = fmaf(e2, f1, of[mt][rb][2]);
                    of[mt][rb][3] = fmaf(e3, f1, of[mt][rb][3]);
                }
            }

            #pragma unroll
            for (int mt = 0; mt < 2; mt++) {
                const int row0 = wm * 32 + mt * 16 + rowq;
                #pragma unroll
                for (int rb = 0; rb < 2; rb++) {
                    const int rl = wn * 2 + rb;
                    stage[row0 * 32 + (2 * q) * 4 + rl]           = of[mt][rb][0];
                    stage[row0 * 32 + (2 * q + 1) * 4 + rl]       = of[mt][rb][1];
                    stage[(row0 + 8) * 32 + (2 * q) * 4 + rl]     = of[mt][rb][2];
                    stage[(row0 + 8) * 32 + (2 * q + 1) * 4 + rl] = of[mt][rb][3];
                }
            }
            __syncthreads();

            #pragma unroll
            for (int w = 0; w < 4; w++) {
                int i = tid + w * 256;
                int row = i >> 3, d = i & 7;
                float4 v = *(const float4*)&stage[row * 32 + d * 4];
                *(float4*)&out[(size_t)(rowbase + row) * 512 + d * 64 + slab * 4] = v;
            }
        }
        __syncthreads();       // slot j&1 free for prefetch issued next iter
    }
}

// ============================================================
extern "C" void kernel_launch(void* const* d_in, const int* in_sizes, int n_in,
                              void* d_out, int out_size) {
    const float* x    = (const float*)d_in[0];
    const float* p    = (const float*)d_in[1];
    const float* W    = (const float*)d_in[2];
    const float* bias = (const float*)d_in[3];
    float* out = (float*)d_out;

    int B = in_sizes[0] / NF;                    // 16384

    prep_kernel<<<(B * 64) / 256, 256>>>(x, W, bias);

    cudaFuncSetAttribute(crowds_mma_kernel,
                         cudaFuncAttributeMaxDynamicSharedMemorySize, SM_TOT);
    crowds_mma_kernel<<<B / 128, 256, SM_TOT>>>(p, out);
}

// round 9
// speedup vs baseline: 1.3491x; 1.0002x over previous
#include <cuda_runtime.h>
#include <cuda_fp16.h>
#include <cstdint>

// ============================================================
// x(16384,128) f32, p(16384,8) f32, W(128,4096) f32, b(4096) f32
// logits[b,n] = sum_f x[b,f]*W[f,n],  n = c*512 + d*64 + r
// out[b, d*64+r] = sum_c p[b,c] * softmax_d(logits[b,c,:,r])
//
// fp16 2-term split (x = xh + xl exact, W single-rounded fp16),
// mma.sync m16n8k16 HMMA, columns permuted n' = r*64 + c*8 + d.
// R9: 512 threads / 16 warps (4m x 4n), warp tile 32x64 ->
// 4 warps/SMSP to cover epilogue/LDSM latency; acc 64 regs.
// ============================================================

#define NF 128

// -------- device scratch --------
__device__ __align__(1024) uint8_t g_Wh[32u * 32768];    // [slab*2+kh][256n][8ch][16B] fp16
__device__ __align__(1024) uint8_t g_Xhi[128u * 32768];  // [rowblk][128r][16ch][16B] fp16
__device__ __align__(1024) uint8_t g_Xlo[128u * 32768];
__device__ __align__(16) float g_biasp[4096];

// -------- smem byte offsets --------
#define SM_XHI   0
#define SM_XLO   32768
#define SM_W     65536            // 2 slots x 32768
#define SM_BIAS  131072           // 16384
#define SM_STAGE 147456           // 16384 (dedicated)
#define SM_P     163840           // 4096
#define SM_TOT   167936

__device__ __forceinline__ uint32_t smem_u32(const void* p) {
    return (uint32_t)__cvta_generic_to_shared(p);
}
__device__ __forceinline__ void cp16(uint32_t dst, const void* src) {
    asm volatile("cp.async.cg.shared.global [%0], [%1], 16;" :: "r"(dst), "l"(src));
}
#define LDSM4(r, a) \
    asm volatile("ldmatrix.sync.aligned.m8n8.x4.shared.b16 {%0,%1,%2,%3}, [%4];" \
        : "=r"((r)[0]), "=r"((r)[1]), "=r"((r)[2]), "=r"((r)[3]) : "r"(a))

__device__ __forceinline__ void mma16816h(float* c, const uint32_t* a,
                                          uint32_t b0, uint32_t b1) {
    asm volatile(
        "mma.sync.aligned.m16n8k16.row.col.f32.f16.f16.f32 "
        "{%0,%1,%2,%3}, {%4,%5,%6,%7}, {%8,%9}, {%0,%1,%2,%3};"
        : "+f"(c[0]), "+f"(c[1]), "+f"(c[2]), "+f"(c[3])
        : "r"(a[0]), "r"(a[1]), "r"(a[2]), "r"(a[3]), "r"(b0), "r"(b1));
}
__device__ __forceinline__ uint32_t pack2h(float a, float b) {
    __half2 h;
    h.x = __float2half_rn(a);
    h.y = __float2half_rn(b);
    return *reinterpret_cast<uint32_t*>(&h);
}

// ============================================================
// Merged prep: W -> permuted fp16 image; x -> fp16 hi/lo split
// images; bias -> permuted.
// ============================================================
__global__ void prep_kernel(const float* __restrict__ X,
                            const float* __restrict__ W,
                            const float* __restrict__ bias) {
    int idx = blockIdx.x * 256 + threadIdx.x;   // 0 .. 1048575

    if (idx < 4096) {
        int n = idx;
        int c = n >> 9, d = (n >> 6) & 7, r = n & 63;
        g_biasp[r * 64 + c * 8 + d] = bias[n];
    }

    if (idx < 64 * 4096) {                      // W items
        int f2 = (idx >> 12) * 2;
        int n  = idx & 4095;
        float w0 = W[(size_t)f2 * 4096 + n];
        float w1 = W[(size_t)(f2 + 1) * 4096 + n];
        int c = n >> 9, d = (n >> 6) & 7, r = n & 63;
        int np = r * 64 + c * 8 + d;            // permuted column
        int slab = np >> 8, nl = np & 255;
        int kh = f2 >> 6, kl = f2 & 63;
        int ch = kl >> 3;
        uint32_t off = (uint32_t)(nl * 128 + (((ch ^ (nl & 7)) & 7) << 4) + (kl & 7) * 2);
        *(uint32_t*)(g_Wh + ((size_t)slab * 2 + kh) * 32768 + off) = pack2h(w0, w1);
    }

    {
        int row = idx >> 6;
        int k2  = (idx & 63) * 2;
        float2 v = *reinterpret_cast<const float2*>(X + (size_t)row * NF + k2);
        float h0 = __half2float(__float2half_rn(v.x));
        float h1 = __half2float(__float2half_rn(v.y));
        int blk = row >> 7, rl = row & 127;
        int ch = k2 >> 3;
        uint32_t off = (uint32_t)(rl * 256 + ((ch ^ (rl & 7)) << 4) + (k2 & 7) * 2);
        *(uint32_t*)(g_Xhi + (size_t)blk * 32768 + off) = pack2h(v.x, v.y);
        *(uint32_t*)(g_Xlo + (size_t)blk * 32768 + off) = pack2h(v.x - h0, v.y - h1);
    }
}

// ============================================================
// Main kernel: 128 CTAs x 512 threads, warp grid 4(m) x 4(n)
// ============================================================
__global__ __launch_bounds__(512, 1)
void crowds_mma_kernel(const float* __restrict__ p, float* __restrict__ out) {
    extern __shared__ __align__(1024) uint8_t smem[];
    const uint32_t sb = smem_u32(smem);
    float* biasS = (float*)(smem + SM_BIAS);
    float* psS   = (float*)(smem + SM_P);
    float* stage = (float*)(smem + SM_STAGE);

    const int tid = threadIdx.x, lane = tid & 31, warp = tid >> 5;
    const int wm = warp >> 2, wn = warp & 3;    // warp tile 32 x 64
    const int rowbase = blockIdx.x * 128;

    // ---- initial loads: X hi/lo, W image 0, bias; p transpose ----
    {
        const uint8_t* gxh = g_Xhi + (size_t)blockIdx.x * 32768;
        const uint8_t* gxl = g_Xlo + (size_t)blockIdx.x * 32768;
        #pragma unroll
        for (int i = 0; i < 4; i++) {
            int o = (tid + i * 512) * 16;
            cp16(sb + SM_XHI + o, gxh + o);
            cp16(sb + SM_XLO + o, gxl + o);
            cp16(sb + SM_W + o, g_Wh + o);
        }
        #pragma unroll
        for (int i = 0; i < 2; i++) {
            int o = (tid + i * 512) * 16;
            cp16(sb + SM_BIAS + o, (const uint8_t*)g_biasp + o);
        }
        asm volatile("cp.async.commit_group;");
        #pragma unroll
        for (int i = 0; i < 2; i++) {
            int ii = tid + i * 512;
            int row = ii >> 3, c = ii & 7;
            psS[c * 128 + row] = p[(size_t)(rowbase + row) * 8 + c];
        }
    }

    float acc[2][8][4];

    for (int j = 0; j < 32; j++) {
        const int slab = j >> 1, kh = j & 1, slot = j & 1;

        // prefetch next W image
        if (j + 1 < 32) {
            const uint8_t* sh = g_Wh + (size_t)(j + 1) * 32768;
            uint32_t dst = sb + SM_W + ((j + 1) & 1) * 32768;
            #pragma unroll
            for (int i = 0; i < 4; i++) {
                int o = (tid + i * 512) * 16;
                cp16(dst + o, sh + o);
            }
            asm volatile("cp.async.commit_group;");
            asm volatile("cp.async.wait_group 1;");
        } else {
            asm volatile("cp.async.wait_group 0;");
        }
        __syncthreads();

        if (kh == 0) {
            #pragma unroll
            for (int mt = 0; mt < 2; mt++)
                #pragma unroll
                for (int nt = 0; nt < 8; nt++)
                    #pragma unroll
                    for (int e = 0; e < 4; e++) acc[mt][nt][e] = 0.f;
        }

        const uint32_t wslot = sb + SM_W + slot * 32768;
        const int arow_base = wm * 32 + (lane & 7) + ((lane >> 3) & 1) * 8;
        const int bn0 = wn * 64 + (lane & 7) + ((lane >> 4) << 3);

        #pragma unroll
        for (int ks = 0; ks < 4; ks++) {
            uint32_t ahi[2][4], alo[2][4];
            const int xch = kh * 8 + ks * 2 + (lane >> 4);
            #pragma unroll
            for (int mt = 0; mt < 2; mt++) {
                int row = arow_base + mt * 16;
                uint32_t aoff = (uint32_t)(row * 256 + ((xch ^ (row & 7)) << 4));
                LDSM4(ahi[mt], sb + SM_XHI + aoff);
                LDSM4(alo[mt], sb + SM_XLO + aoff);
            }
            const int bch = ks * 2 + ((lane >> 3) & 1);
            #pragma unroll
            for (int t2 = 0; t2 < 4; t2++) {
                uint32_t bh[4];
                int n = bn0 + t2 * 16;
                uint32_t boff = (uint32_t)(n * 128 + (((bch ^ (n & 7)) & 7) << 4));
                LDSM4(bh, wslot + boff);
                #pragma unroll
                for (int mt = 0; mt < 2; mt++)
                    #pragma unroll
                    for (int hf = 0; hf < 2; hf++) {
                        float* cacc = acc[mt][t2 * 2 + hf];
                        mma16816h(cacc, ahi[mt], bh[hf * 2], bh[hf * 2 + 1]);
                        mma16816h(cacc, alo[mt], bh[hf * 2], bh[hf * 2 + 1]);
                    }
            }
        }

        // ---- epilogue at slab end: softmax over d (quad shuffles) + p ----
        // This warp's 64 cols = one r value: r = slab*4 + wn; nt == c.
        if (kh == 1) {
            const int q = lane & 3, rowq = lane >> 2;
            float of[2][4];
            #pragma unroll
            for (int mt = 0; mt < 2; mt++)
                #pragma unroll
                for (int e = 0; e < 4; e++) of[mt][e] = 0.f;

            #pragma unroll
            for (int mt = 0; mt < 2; mt++) {
                const int row0 = wm * 32 + mt * 16 + rowq;
                #pragma unroll
                for (int c = 0; c < 8; c++) {
                    const int nb_abs = slab * 256 + wn * 64 + c * 8;
                    float2 bv = *(const float2*)&biasS[nb_abs + q * 2];
                    float e0 = __expf(acc[mt][c][0] + bv.x);
                    float e1 = __expf(acc[mt][c][1] + bv.y);
                    float e2 = __expf(acc[mt][c][2] + bv.x);
                    float e3 = __expf(acc[mt][c][3] + bv.y);
                    float s0 = e0 + e1, s1 = e2 + e3;
                    s0 += __shfl_xor_sync(0xffffffffu, s0, 1);
                    s0 += __shfl_xor_sync(0xffffffffu, s0, 2);
                    s1 += __shfl_xor_sync(0xffffffffu, s1, 1);
                    s1 += __shfl_xor_sync(0xffffffffu, s1, 2);
                    float f0 = __fdividef(psS[c * 128 + row0], s0);
                    float f1 = __fdividef(psS[c * 128 + row0 + 8], s1);
                    of[mt][0] = fmaf(e0, f0, of[mt][0]);
                    of[mt][1] = fmaf(e1, f0, of[mt][1]);
                    of[mt][2] = fmaf(e2, f1, of[mt][2]);
                    of[mt][3] = fmaf(e3, f1, of[mt][3]);
                }
            }

            #pragma unroll
            for (int mt = 0; mt < 2; mt++) {
                const int row0 = wm * 32 + mt * 16 + rowq;
                stage[row0 * 32 + (2 * q) * 4 + wn]           = of[mt][0];
                stage[row0 * 32 + (2 * q + 1) * 4 + wn]       = of[mt][1];
                stage[(row0 + 8) * 32 + (2 * q) * 4 + wn]     = of[mt][2];
                stage[(row0 + 8) * 32 + (2 * q + 1) * 4 + wn] = of[mt][3];
            }
            __syncthreads();

            #pragma unroll
            for (int w = 0; w < 2; w++) {
                int i = tid + w * 512;
                int row = i >> 3, d = i & 7;
                float4 v = *(const float4*)&stage[row * 32 + d * 4];
                *(float4*)&out[(size_t)(rowbase + row) * 512 + d * 64 + slab * 4] = v;
            }
        }
        __syncthreads();       // W slot (j&1) free for next prefetch; stage safe
    }
}

// ============================================================
extern "C" void kernel_launch(void* const* d_in, const int* in_sizes, int n_in,
                              void* d_out, int out_size) {
    const float* x    = (const float*)d_in[0];
    const float* p    = (const float*)d_in[1];
    const float* W    = (const float*)d_in[2];
    const float* bias = (const float*)d_in[3];
    float* out = (float*)d_out;

    int B = in_sizes[0] / NF;                    // 16384

    prep_kernel<<<(B * 64) / 256, 256>>>(x, W, bias);

    cudaFuncSetAttribute(crowds_mma_kernel,
                         cudaFuncAttributeMaxDynamicSharedMemorySize, SM_TOT);
    crowds_mma_kernel<<<B / 128, 512, SM_TOT>>>(p, out);
}

// round 10
// speedup vs baseline: 1.8098x; 1.3415x over previous
#include <cuda_runtime.h>
#include <cuda_fp16.h>
#include <cstdint>

// ============================================================
// x(16384,128) f32, p(16384,8) f32, W(128,4096) f32, b(4096) f32
// logits[b,n] = sum_f x[b,f]*W[f,n],  n = c*512 + d*64 + r
// out[b, d*64+r] = sum_c p[b,c] * softmax_d(logits[b,c,:,r])
//
// R10: SINGLE-term fp16 mma.sync (x and W both fp16-rounded;
// calibrated vs R8 W-only rounding = 1.78e-5 -> predicted ~3e-5),
// columns permuted n' = r*64 + c*8 + d. Full-slab iterations:
// 16 iters x 1 barrier, prefetch + output stores overlapped with
// MMA phase, double-buffered stage.
// ============================================================

#define NF 128

// -------- device scratch --------
__device__ __align__(1024) uint8_t g_Wh[32u * 32768];   // [slab][kh][256n][8ch][16B]
__device__ __align__(1024) uint8_t g_Xh[128u * 32768];  // [rowblk][128r][16ch][16B]
__device__ __align__(16) float g_biasp[4096];

// -------- smem byte offsets --------
#define SM_XH    0                 // 32768
#define SM_W     32768             // 2 slots x 65536 (full slab images)
#define SM_BIAS  163840            // 16384
#define SM_STAGE 180224            // 2 x 16384
#define SM_P     212992            // 4096
#define SM_TOT   217088

__device__ __forceinline__ uint32_t smem_u32(const void* p) {
    return (uint32_t)__cvta_generic_to_shared(p);
}
__device__ __forceinline__ void cp16(uint32_t dst, const void* src) {
    asm volatile("cp.async.cg.shared.global [%0], [%1], 16;" :: "r"(dst), "l"(src));
}
#define LDSM4(r, a) \
    asm volatile("ldmatrix.sync.aligned.m8n8.x4.shared.b16 {%0,%1,%2,%3}, [%4];" \
        : "=r"((r)[0]), "=r"((r)[1]), "=r"((r)[2]), "=r"((r)[3]) : "r"(a))

__device__ __forceinline__ void mma16816h(float* c, const uint32_t* a,
                                          uint32_t b0, uint32_t b1) {
    asm volatile(
        "mma.sync.aligned.m16n8k16.row.col.f32.f16.f16.f32 "
        "{%0,%1,%2,%3}, {%4,%5,%6,%7}, {%8,%9}, {%0,%1,%2,%3};"
        : "+f"(c[0]), "+f"(c[1]), "+f"(c[2]), "+f"(c[3])
        : "r"(a[0]), "r"(a[1]), "r"(a[2]), "r"(a[3]), "r"(b0), "r"(b1));
}
__device__ __forceinline__ uint32_t pack2h(float a, float b) {
    __half2 h;
    h.x = __float2half_rn(a);
    h.y = __float2half_rn(b);
    return *reinterpret_cast<uint32_t*>(&h);
}

// ============================================================
// Merged prep: W -> permuted fp16 image; x -> fp16 image;
// bias -> permuted.
// ============================================================
__global__ void prep_kernel(const float* __restrict__ X,
                            const float* __restrict__ W,
                            const float* __restrict__ bias) {
    int idx = blockIdx.x * 256 + threadIdx.x;   // 0 .. 1048575

    if (idx < 4096) {
        int n = idx;
        int c = n >> 9, d = (n >> 6) & 7, r = n & 63;
        g_biasp[r * 64 + c * 8 + d] = bias[n];
    }

    if (idx < 64 * 4096) {                      // W items
        int f2 = (idx >> 12) * 2;
        int n  = idx & 4095;
        float w0 = W[(size_t)f2 * 4096 + n];
        float w1 = W[(size_t)(f2 + 1) * 4096 + n];
        int c = n >> 9, d = (n >> 6) & 7, r = n & 63;
        int np = r * 64 + c * 8 + d;            // permuted column
        int slab = np >> 8, nl = np & 255;
        int kh = f2 >> 6, kl = f2 & 63;
        int ch = kl >> 3;
        uint32_t off = (uint32_t)(nl * 128 + (((ch ^ (nl & 7)) & 7) << 4) + (kl & 7) * 2);
        *(uint32_t*)(g_Wh + ((size_t)slab * 2 + kh) * 32768 + off) = pack2h(w0, w1);
    }

    {
        int row = idx >> 6;
        int k2  = (idx & 63) * 2;
        float2 v = *reinterpret_cast<const float2*>(X + (size_t)row * NF + k2);
        int blk = row >> 7, rl = row & 127;
        int ch = k2 >> 3;
        uint32_t off = (uint32_t)(rl * 256 + ((ch ^ (rl & 7)) << 4) + (k2 & 7) * 2);
        *(uint32_t*)(g_Xh + (size_t)blk * 32768 + off) = pack2h(v.x, v.y);
    }
}

// ============================================================
// Main kernel: 128 CTAs x 256 threads, warp grid 4(m) x 2(n)
// ============================================================
__global__ __launch_bounds__(256, 1)
void crowds_mma_kernel(const float* __restrict__ p, float* __restrict__ out) {
    extern __shared__ __align__(1024) uint8_t smem[];
    const uint32_t sb = smem_u32(smem);
    float* biasS = (float*)(smem + SM_BIAS);
    float* psS   = (float*)(smem + SM_P);

    const int tid = threadIdx.x, lane = tid & 31, warp = tid >> 5;
    const int wm = warp >> 1, wn = warp & 1;    // warp tile 32 x 128
    const int rowbase = blockIdx.x * 128;

    // ---- prologue: X image, W slab 0, bias (one cp.async group); p ----
    {
        const uint8_t* gx = g_Xh + (size_t)blockIdx.x * 32768;
        #pragma unroll
        for (int i = 0; i < 8; i++) {
            int o = (tid + i * 256) * 16;
            cp16(sb + SM_XH + o, gx + o);
        }
        #pragma unroll
        for (int i = 0; i < 16; i++) {
            int o = (tid + i * 256) * 16;
            cp16(sb + SM_W + o, g_Wh + o);
        }
        #pragma unroll
        for (int i = 0; i < 4; i++) {
            int o = (tid + i * 256) * 16;
            cp16(sb + SM_BIAS + o, (const uint8_t*)g_biasp + o);
        }
        asm volatile("cp.async.commit_group;");
        #pragma unroll
        for (int i = 0; i < 4; i++) {
            int ii = tid + i * 256;
            int row = ii >> 3, c = ii & 7;
            psS[c * 128 + row] = p[(size_t)(rowbase + row) * 8 + c];
        }
    }

    float acc[2][16][4];

    for (int j = 0; j < 16; j++) {
        // own cp.async done (W slab j [+ prologue at j=0]); then make all
        // threads' fills visible AND retire all iter j-1 readers/stores.
        asm volatile("cp.async.wait_group 0;");
        __syncthreads();

        // prefetch W slab j+1 into the other slot (overlaps MMA phase)
        if (j + 1 < 16) {
            const uint8_t* src = g_Wh + (size_t)(j + 1) * 65536;
            uint32_t dst = sb + SM_W + ((j + 1) & 1) * 65536;
            #pragma unroll
            for (int i = 0; i < 16; i++) {
                int o = (tid + i * 256) * 16;
                cp16(dst + o, src + o);
            }
            asm volatile("cp.async.commit_group;");
        }

        // deferred output stores for slab j-1 (overlap MMA phase)
        if (j > 0) {
            const float* stg = (const float*)(smem + SM_STAGE + ((j - 1) & 1) * 16384);
            #pragma unroll
            for (int w = 0; w < 4; w++) {
                int i = tid + w * 256;
                int row = i >> 3, d = i & 7;
                float4 v = *(const float4*)&stg[row * 32 + d * 4];
                *(float4*)&out[(size_t)(rowbase + row) * 512 + d * 64 + (j - 1) * 4] = v;
            }
        }

        #pragma unroll
        for (int mt = 0; mt < 2; mt++)
            #pragma unroll
            for (int nt = 0; nt < 16; nt++)
                #pragma unroll
                for (int e = 0; e < 4; e++) acc[mt][nt][e] = 0.f;

        const uint32_t wslot = sb + SM_W + (j & 1) * 65536;
        const int arow_base = wm * 32 + (lane & 7) + ((lane >> 3) & 1) * 8;
        const int bn0 = wn * 128 + (lane & 7) + ((lane >> 4) << 3);

        #pragma unroll
        for (int kh = 0; kh < 2; kh++) {
            const uint32_t wbase = wslot + kh * 32768;
            #pragma unroll
            for (int ks = 0; ks < 4; ks++) {
                uint32_t ah[2][4];
                const int xch = kh * 8 + ks * 2 + (lane >> 4);
                #pragma unroll
                for (int mt = 0; mt < 2; mt++) {
                    int row = arow_base + mt * 16;
                    uint32_t aoff = (uint32_t)(row * 256 + ((xch ^ (row & 7)) << 4));
                    LDSM4(ah[mt], sb + SM_XH + aoff);
                }
                const int bch = ks * 2 + ((lane >> 3) & 1);
                #pragma unroll
                for (int nb = 0; nb < 2; nb++) {
                    #pragma unroll
                    for (int t2 = 0; t2 < 4; t2++) {
                        uint32_t bh[4];
                        int n = bn0 + nb * 64 + t2 * 16;
                        uint32_t boff = (uint32_t)(n * 128 + (((bch ^ (n & 7)) & 7) << 4));
                        LDSM4(bh, wbase + boff);
                        #pragma unroll
                        for (int mt = 0; mt < 2; mt++)
                            #pragma unroll
                            for (int hf = 0; hf < 2; hf++)
                                mma16816h(acc[mt][nb * 8 + t2 * 2 + hf],
                                          ah[mt], bh[hf * 2], bh[hf * 2 + 1]);
                    }
                }
            }
        }

        // ---- epilogue: softmax over d (quad shuffles) + p-weighting ----
        {
            float* stage = (float*)(smem + SM_STAGE + (j & 1) * 16384);
            const int q = lane & 3, rowq = lane >> 2;
            float of[2][2][4];
            #pragma unroll
            for (int mt = 0; mt < 2; mt++)
                #pragma unroll
                for (int rb = 0; rb < 2; rb++)
                    #pragma unroll
                    for (int e = 0; e < 4; e++) of[mt][rb][e] = 0.f;

            #pragma unroll
            for (int mt = 0; mt < 2; mt++) {
                const int row0 = wm * 32 + mt * 16 + rowq;
                #pragma unroll
                for (int nt = 0; nt < 16; nt++) {
                    const int c = nt & 7, rb = nt >> 3;
                    const int nb_abs = j * 256 + wn * 128 + nt * 8;
                    float2 bv = *(const float2*)&biasS[nb_abs + q * 2];
                    float e0 = __expf(acc[mt][nt][0] + bv.x);
                    float e1 = __expf(acc[mt][nt][1] + bv.y);
                    float e2 = __expf(acc[mt][nt][2] + bv.x);
                    float e3 = __expf(acc[mt][nt][3] + bv.y);
                    float s0 = e0 + e1, s1 = e2 + e3;
                    s0 += __shfl_xor_sync(0xffffffffu, s0, 1);
                    s0 += __shfl_xor_sync(0xffffffffu, s0, 2);
                    s1 += __shfl_xor_sync(0xffffffffu, s1, 1);
                    s1 += __shfl_xor_sync(0xffffffffu, s1, 2);
                    float f0 = __fdividef(psS[c * 128 + row0], s0);
                    float f1 = __fdividef(psS[c * 128 + row0 + 8], s1);
                    of[mt][rb][0] = fmaf(e0, f0, of[mt][rb][0]);
                    of[mt][rb][1] = fmaf(e1, f0, of[mt][rb][1]);
                    of[mt][rb][2] = fmaf(e2, f1, of[mt][rb][2]);
                    of[mt][rb][3] = fmaf(e3, f1, of[mt][rb][3]);
                }
            }

            #pragma unroll
            for (int mt = 0; mt < 2; mt++) {
                const int row0 = wm * 32 + mt * 16 + rowq;
                #pragma unroll
                for (int rb = 0; rb < 2; rb++) {
                    const int rl = wn * 2 + rb;
                    stage[row0 * 32 + (2 * q) * 4 + rl]           = of[mt][rb][0];
                    stage[row0 * 32 + (2 * q + 1) * 4 + rl]       = of[mt][rb][1];
                    stage[(row0 + 8) * 32 + (2 * q) * 4 + rl]     = of[mt][rb][2];
                    stage[(row0 + 8) * 32 + (2 * q + 1) * 4 + rl] = of[mt][rb][3];
                }
            }
        }
    }

    // ---- final stores: slab 15 (stage buffer 1) ----
    __syncthreads();
    {
        const float* stg = (const float*)(smem + SM_STAGE + 16384);
        #pragma unroll
        for (int w = 0; w < 4; w++) {
            int i = tid + w * 256;
            int row = i >> 3, d = i & 7;
            float4 v = *(const float4*)&stg[row * 32 + d * 4];
            *(float4*)&out[(size_t)(rowbase + row) * 512 + d * 64 + 15 * 4] = v;
        }
    }
}

// ============================================================
extern "C" void kernel_launch(void* const* d_in, const int* in_sizes, int n_in,
                              void* d_out, int out_size) {
    const float* x    = (const float*)d_in[0];
    const float* p    = (const float*)d_in[1];
    const float* W    = (const float*)d_in[2];
    const float* bias = (const float*)d_in[3];
    float* out = (float*)d_out;

    int B = in_sizes[0] / NF;                    // 16384

    prep_kernel<<<(B * 64) / 256, 256>>>(x, W, bias);

    cudaFuncSetAttribute(crowds_mma_kernel,
                         cudaFuncAttributeMaxDynamicSharedMemorySize, SM_TOT);
    crowds_mma_kernel<<<B / 128, 256, SM_TOT>>>(p, out);
}

// round 11
// speedup vs baseline: 1.8739x; 1.0354x over previous
#include <cuda_runtime.h>
#include <cuda_fp16.h>
#include <cstdint>

// ============================================================
// x(16384,128) f32, p(16384,8) f32, W(128,4096) f32, b(4096) f32
// logits[b,n] = sum_f x[b,f]*W[f,n],  n = c*512 + d*64 + r
// out[b, d*64+r] = sum_c p[b,c] * softmax_d(logits[b,c,:,r])
//
// R11: single-term fp16 mma.sync, columns permuted n'=r*64+c*8+d.
//  - A fragments loaded ONCE into 64 regs (slab-invariant X tile)
//  - per-slab loop over eight 16-col B groups, K innermost:
//    MMA(g) issued, then epilogue(g-1) executes while HMMA(g) in
//    flight (double-buffered group accumulators) -> tensor pipe
//    overlaps MUFU/SHFL epilogue within each warp.
//  - 1 barrier/slab, prefetch + deferred stores overlap MMA.
// ============================================================

#define NF 128

// -------- device scratch --------
__device__ __align__(1024) uint8_t g_Wh[32u * 32768];   // [slab][kh][256n][8ch][16B]
__device__ __align__(1024) uint8_t g_Xh[128u * 32768];  // [rowblk][128r][16ch][16B]
__device__ __align__(16) float g_biasp[4096];

// -------- smem byte offsets --------
#define SM_XH    0                 // 32768
#define SM_W     32768             // 2 slots x 65536 (full slab images)
#define SM_BIAS  163840            // 16384
#define SM_STAGE 180224            // 2 x 16384
#define SM_P     212992            // 4096
#define SM_TOT   217088

__device__ __forceinline__ uint32_t smem_u32(const void* p) {
    return (uint32_t)__cvta_generic_to_shared(p);
}
__device__ __forceinline__ void cp16(uint32_t dst, const void* src) {
    asm volatile("cp.async.cg.shared.global [%0], [%1], 16;" :: "r"(dst), "l"(src));
}
#define LDSM4(r, a) \
    asm volatile("ldmatrix.sync.aligned.m8n8.x4.shared.b16 {%0,%1,%2,%3}, [%4];" \
        : "=r"((r)[0]), "=r"((r)[1]), "=r"((r)[2]), "=r"((r)[3]) : "r"(a))

__device__ __forceinline__ void mma16816h(float* c, const uint32_t* a,
                                          uint32_t b0, uint32_t b1) {
    asm volatile(
        "mma.sync.aligned.m16n8k16.row.col.f32.f16.f16.f32 "
        "{%0,%1,%2,%3}, {%4,%5,%6,%7}, {%8,%9}, {%0,%1,%2,%3};"
        : "+f"(c[0]), "+f"(c[1]), "+f"(c[2]), "+f"(c[3])
        : "r"(a[0]), "r"(a[1]), "r"(a[2]), "r"(a[3]), "r"(b0), "r"(b1));
}
__device__ __forceinline__ uint32_t pack2h(float a, float b) {
    __half2 h;
    h.x = __float2half_rn(a);
    h.y = __float2half_rn(b);
    return *reinterpret_cast<uint32_t*>(&h);
}

// ============================================================
// Merged prep: W -> permuted fp16 image; x -> fp16 image;
// bias -> permuted.
// ============================================================
__global__ void prep_kernel(const float* __restrict__ X,
                            const float* __restrict__ W,
                            const float* __restrict__ bias) {
    int idx = blockIdx.x * 256 + threadIdx.x;   // 0 .. 1048575

    if (idx < 4096) {
        int n = idx;
        int c = n >> 9, d = (n >> 6) & 7, r = n & 63;
        g_biasp[r * 64 + c * 8 + d] = bias[n];
    }

    if (idx < 64 * 4096) {                      // W items
        int f2 = (idx >> 12) * 2;
        int n  = idx & 4095;
        float w0 = W[(size_t)f2 * 4096 + n];
        float w1 = W[(size_t)(f2 + 1) * 4096 + n];
        int c = n >> 9, d = (n >> 6) & 7, r = n & 63;
        int np = r * 64 + c * 8 + d;            // permuted column
        int slab = np >> 8, nl = np & 255;
        int kh = f2 >> 6, kl = f2 & 63;
        int ch = kl >> 3;
        uint32_t off = (uint32_t)(nl * 128 + (((ch ^ (nl & 7)) & 7) << 4) + (kl & 7) * 2);
        *(uint32_t*)(g_Wh + ((size_t)slab * 2 + kh) * 32768 + off) = pack2h(w0, w1);
    }

    {
        int row = idx >> 6;
        int k2  = (idx & 63) * 2;
        float2 v = *reinterpret_cast<const float2*>(X + (size_t)row * NF + k2);
        int blk = row >> 7, rl = row & 127;
        int ch = k2 >> 3;
        uint32_t off = (uint32_t)(rl * 256 + ((ch ^ (rl & 7)) << 4) + (k2 & 7) * 2);
        *(uint32_t*)(g_Xh + (size_t)blk * 32768 + off) = pack2h(v.x, v.y);
    }
}

// ============================================================
// Main kernel: 128 CTAs x 256 threads, warp grid 4(m) x 2(n)
// ============================================================
__global__ __launch_bounds__(256, 1)
void crowds_mma_kernel(const float* __restrict__ p, float* __restrict__ out) {
    extern __shared__ __align__(1024) uint8_t smem[];
    const uint32_t sb = smem_u32(smem);
    float* biasS = (float*)(smem + SM_BIAS);
    float* psS   = (float*)(smem + SM_P);

    const int tid = threadIdx.x, lane = tid & 31, warp = tid >> 5;
    const int wm = warp >> 1, wn = warp & 1;    // warp tile 32 x 128
    const int rowbase = blockIdx.x * 128;

    // ---- prologue: X image, W slab 0, bias (one cp.async group); p ----
    {
        const uint8_t* gx = g_Xh + (size_t)blockIdx.x * 32768;
        #pragma unroll
        for (int i = 0; i < 8; i++) {
            int o = (tid + i * 256) * 16;
            cp16(sb + SM_XH + o, gx + o);
        }
        #pragma unroll
        for (int i = 0; i < 16; i++) {
            int o = (tid + i * 256) * 16;
            cp16(sb + SM_W + o, g_Wh + o);
        }
        #pragma unroll
        for (int i = 0; i < 4; i++) {
            int o = (tid + i * 256) * 16;
            cp16(sb + SM_BIAS + o, (const uint8_t*)g_biasp + o);
        }
        asm volatile("cp.async.commit_group;");
        #pragma unroll
        for (int i = 0; i < 4; i++) {
            int ii = tid + i * 256;
            int row = ii >> 3, c = ii & 7;
            psS[c * 128 + row] = p[(size_t)(rowbase + row) * 8 + c];
        }
    }

    asm volatile("cp.async.wait_group 0;");
    __syncthreads();

    // ---- A fragments for the whole kernel (slab-invariant) ----
    const int arow_base = wm * 32 + (lane & 7) + ((lane >> 3) & 1) * 8;
    const int bn0 = wn * 128 + (lane & 7) + ((lane >> 4) << 3);
    const int q = lane & 3, rowq = lane >> 2;

    uint32_t ah[8][2][4];
    #pragma unroll
    for (int ks8 = 0; ks8 < 8; ks8++) {
        const int xch = ks8 * 2 + (lane >> 4);
        #pragma unroll
        for (int mt = 0; mt < 2; mt++) {
            int row = arow_base + mt * 16;
            uint32_t aoff = (uint32_t)(row * 256 + ((xch ^ (row & 7)) << 4));
            LDSM4(ah[ks8][mt], sb + SM_XH + aoff);
        }
    }

    float accb[2][2][2][4];   // [buf][mt][hf][4]
    float of[2][2][4];        // [mt][rb][4]

    for (int j = 0; j < 16; j++) {
        if (j > 0) {
            asm volatile("cp.async.wait_group 0;");
            __syncthreads();
        }

        // prefetch W slab j+1 (overlaps MMA+epilogue of slab j)
        if (j + 1 < 16) {
            const uint8_t* src = g_Wh + (size_t)(j + 1) * 65536;
            uint32_t dst = sb + SM_W + ((j + 1) & 1) * 65536;
            #pragma unroll
            for (int i = 0; i < 16; i++) {
                int o = (tid + i * 256) * 16;
                cp16(dst + o, src + o);
            }
            asm volatile("cp.async.commit_group;");
        }

        // deferred output stores for slab j-1 (overlap MMA phase)
        if (j > 0) {
            const float* stg = (const float*)(smem + SM_STAGE + ((j - 1) & 1) * 16384);
            #pragma unroll
            for (int w = 0; w < 4; w++) {
                int i = tid + w * 256;
                int row = i >> 3, d = i & 7;
                float4 v = *(const float4*)&stg[row * 32 + d * 4];
                *(float4*)&out[(size_t)(rowbase + row) * 512 + d * 64 + (j - 1) * 4] = v;
            }
        }

        #pragma unroll
        for (int mt = 0; mt < 2; mt++)
            #pragma unroll
            for (int rb = 0; rb < 2; rb++)
                #pragma unroll
                for (int e = 0; e < 4; e++) of[mt][rb][e] = 0.f;

        const uint32_t wslot = sb + SM_W + (j & 1) * 65536;

        // ---- 8 groups of 16 columns; MMA(g) then epilogue(g-1) ----
        #pragma unroll
        for (int g = 0; g < 8; g++) {
            float* ag = &accb[g & 1][0][0][0];
            #pragma unroll
            for (int e = 0; e < 16; e++) ag[e] = 0.f;

            const int n = bn0 + g * 16;
            #pragma unroll
            for (int ks8 = 0; ks8 < 8; ks8++) {
                uint32_t bh[4];
                const int bch = (ks8 & 3) * 2 + ((lane >> 3) & 1);
                uint32_t boff = (uint32_t)((ks8 >> 2) * 32768 + n * 128
                                           + (((bch ^ (n & 7)) & 7) << 4));
                LDSM4(bh, wslot + boff);
                #pragma unroll
                for (int mt = 0; mt < 2; mt++)
                    #pragma unroll
                    for (int hf = 0; hf < 2; hf++)
                        mma16816h(&accb[g & 1][mt][hf][0],
                                  ah[ks8][mt], bh[hf * 2], bh[hf * 2 + 1]);
            }

            // epilogue of previous group while this group's HMMAs fly
            if (g > 0) {
                const int pg = g - 1, rb = pg >> 2;
                #pragma unroll
                for (int hf = 0; hf < 2; hf++) {
                    const int c = (pg & 3) * 2 + hf;
                    const int nb_abs = j * 256 + wn * 128 + pg * 16 + hf * 8;
                    float2 bv = *(const float2*)&biasS[nb_abs + q * 2];
                    #pragma unroll
                    for (int mt = 0; mt < 2; mt++) {
                        const int row0 = wm * 32 + mt * 16 + rowq;
                        const float* a4 = &accb[pg & 1][mt][hf][0];
                        float e0 = __expf(a4[0] + bv.x);
                        float e1 = __expf(a4[1] + bv.y);
                        float e2 = __expf(a4[2] + bv.x);
                        float e3 = __expf(a4[3] + bv.y);
                        float s0 = e0 + e1, s1 = e2 + e3;
                        s0 += __shfl_xor_sync(0xffffffffu, s0, 1);
                        s0 += __shfl_xor_sync(0xffffffffu, s0, 2);
                        s1 += __shfl_xor_sync(0xffffffffu, s1, 1);
                        s1 += __shfl_xor_sync(0xffffffffu, s1, 2);
                        float f0 = __fdividef(psS[c * 128 + row0], s0);
                        float f1 = __fdividef(psS[c * 128 + row0 + 8], s1);
                        of[mt][rb][0] = fmaf(e0, f0, of[mt][rb][0]);
                        of[mt][rb][1] = fmaf(e1, f0, of[mt][rb][1]);
                        of[mt][rb][2] = fmaf(e2, f1, of[mt][rb][2]);
                        of[mt][rb][3] = fmaf(e3, f1, of[mt][rb][3]);
                    }
                }
            }
        }
        // last group epilogue
        {
            const int pg = 7, rb = 1;
            #pragma unroll
            for (int hf = 0; hf < 2; hf++) {
                const int c = (pg & 3) * 2 + hf;
                const int nb_abs = j * 256 + wn * 128 + pg * 16 + hf * 8;
                float2 bv = *(const float2*)&biasS[nb_abs + q * 2];
                #pragma unroll
                for (int mt = 0; mt < 2; mt++) {
                    const int row0 = wm * 32 + mt * 16 + rowq;
                    const float* a4 = &accb[pg & 1][mt][hf][0];
                    float e0 = __expf(a4[0] + bv.x);
                    float e1 = __expf(a4[1] + bv.y);
                    float e2 = __expf(a4[2] + bv.x);
                    float e3 = __expf(a4[3] + bv.y);
                    float s0 = e0 + e1, s1 = e2 + e3;
                    s0 += __shfl_xor_sync(0xffffffffu, s0, 1);
                    s0 += __shfl_xor_sync(0xffffffffu, s0, 2);
                    s1 += __shfl_xor_sync(0xffffffffu, s1, 1);
                    s1 += __shfl_xor_sync(0xffffffffu, s1, 2);
                    float f0 = __fdividef(psS[c * 128 + row0], s0);
                    float f1 = __fdividef(psS[c * 128 + row0 + 8], s1);
                    of[mt][rb][0] = fmaf(e0, f0, of[mt][rb][0]);
                    of[mt][rb][1] = fmaf(e1, f0, of[mt][rb][1]);
                    of[mt][rb][2] = fmaf(e2, f1, of[mt][rb][2]);
                    of[mt][rb][3] = fmaf(e3, f1, of[mt][rb][3]);
                }
            }
        }

        // ---- write this slab's results into stage[j&1] ----
        {
            float* stage = (float*)(smem + SM_STAGE + (j & 1) * 16384);
            #pragma unroll
            for (int mt = 0; mt < 2; mt++) {
                const int row0 = wm * 32 + mt * 16 + rowq;
                #pragma unroll
                for (int rb = 0; rb < 2; rb++) {
                    const int rl = wn * 2 + rb;
                    stage[row0 * 32 + (2 * q) * 4 + rl]           = of[mt][rb][0];
                    stage[row0 * 32 + (2 * q + 1) * 4 + rl]       = of[mt][rb][1];
                    stage[(row0 + 8) * 32 + (2 * q) * 4 + rl]     = of[mt][rb][2];
                    stage[(row0 + 8) * 32 + (2 * q + 1) * 4 + rl] = of[mt][rb][3];
                }
            }
        }
    }

    // ---- final stores: slab 15 (stage buffer 1) ----
    __syncthreads();
    {
        const float* stg = (const float*)(smem + SM_STAGE + 16384);
        #pragma unroll
        for (int w = 0; w < 4; w++) {
            int i = tid + w * 256;
            int row = i >> 3, d = i & 7;
            float4 v = *(const float4*)&stg[row * 32 + d * 4];
            *(float4*)&out[(size_t)(rowbase + row) * 512 + d * 64 + 15 * 4] = v;
        }
    }
}

// ============================================================
extern "C" void kernel_launch(void* const* d_in, const int* in_sizes, int n_in,
                              void* d_out, int out_size) {
    const float* x    = (const float*)d_in[0];
    const float* p    = (const float*)d_in[1];
    const float* W    = (const float*)d_in[2];
    const float* bias = (const float*)d_in[3];
    float* out = (float*)d_out;

    int B = in_sizes[0] / NF;                    // 16384

    prep_kernel<<<(B * 64) / 256, 256>>>(x, W, bias);

    cudaFuncSetAttribute(crowds_mma_kernel,
                         cudaFuncAttributeMaxDynamicSharedMemorySize, SM_TOT);
    crowds_mma_kernel<<<B / 128, 256, SM_TOT>>>(p, out);
}